// round 5
// baseline (speedup 1.0000x reference)
#include <cuda_runtime.h>
#include <cstdint>

// ---------------------------------------------------------------------------
// PointNet++ (3 SA stages), B=64, N=4096, fp32.
// Round 5: 4ch x 16-sample register tiles (32 FFMA2 per weight LDG),
// multi-group blocks with dynamic smem, stage-0 dup-xyz weight folding.
// ---------------------------------------------------------------------------

static constexpr int B   = 64;
static constexpr int N0  = 4096;
static constexpr int S0  = 128, NSAMP0 = 32;
static constexpr int S1  = 64;
static constexpr int S2  = 32;

// ------------------------- device scratch (no allocs) ----------------------
__device__ float g_nx1[B * S0 * 3];
__device__ float g_nx2[B * S1 * 3];
__device__ float g_nx3[B * S2 * 3];
__device__ int   g_idxbuf[B * S0 * NSAMP0];
__device__ float g_f1[B * S0 * 64];
__device__ float g_f2[B * S1 * 128];

// k-major folded weights: wT[k*Cout + o]. Layer0 folded to 6 rows
// (rows 3..5 = W[:,3:6]+W[:,6:9], since stage-0 feats duplicate abs xyz).
__device__ __align__(16) float g_w0T[6 * 32];     __device__ __align__(16) float g_b0[32];
__device__ __align__(16) float g_w1T[32 * 64];    __device__ __align__(16) float g_b1[64];
__device__ __align__(16) float g_w2T[67 * 128];   __device__ __align__(16) float g_b2[128];
__device__ __align__(16) float g_w3T[128 * 128];  __device__ __align__(16) float g_b3[128];
__device__ __align__(16) float g_w4T[131 * 256];  __device__ __align__(16) float g_b4[256];
__device__ __align__(16) float g_w5T[256 * 256];  __device__ __align__(16) float g_b5[256];

// ------------------------- f32x2 helpers -----------------------------------
typedef unsigned long long u64;

__device__ __forceinline__ u64 pack2(float x) {
    u64 r;
    asm("mov.b64 %0, {%1, %2};" : "=l"(r) : "f"(x), "f"(x));
    return r;
}
__device__ __forceinline__ void unpack2(u64 v, float& lo, float& hi) {
    asm("mov.b64 {%0, %1}, %2;" : "=f"(lo), "=f"(hi) : "l"(v));
}
__device__ __forceinline__ u64 ffma2(u64 a, u64 b, u64 c) {
    u64 d;
    asm("fma.rn.f32x2 %0, %1, %2, %3;" : "=l"(d) : "l"(a), "l"(b), "l"(c));
    return d;
}

// ------------------------- merged BN fold (k-major) ------------------------
struct FoldArgs {
    const float* w[6]; const float* g[6]; const float* be[6];
    const float* rm[6]; const float* rv[6];
    float* wT[6]; float* bias[6];
    int cin[6]; int cout[6];
};

__global__ void fold_all_kernel(FoldArgs a)
{
    int l = blockIdx.y;
    int cin = a.cin[l], cout = a.cout[l];
    const float* w = a.w[l]; const float* g = a.g[l]; const float* be = a.be[l];
    const float* rm = a.rm[l]; const float* rv = a.rv[l];
    float* wT = a.wT[l]; float* bias = a.bias[l];
    int i = blockIdx.x * blockDim.x + threadIdx.x;
    if (i < cout) {
        float s = g[i] * rsqrtf(rv[i] + 1e-5f);
        bias[i] = be[i] - s * rm[i];
    }
    if (l == 0) {
        // fold 9 -> 6 rows: rows 0..2 as-is, rows 3..5 = W[:,3+t] + W[:,6+t]
        int tot = cout * 6;
        for (int e = i; e < tot; e += gridDim.x * blockDim.x) {
            int o = e / 6, k = e - o * 6;
            float s = g[o] * rsqrtf(rv[o] + 1e-5f);
            float val = (k < 3) ? w[o * 9 + k] : (w[o * 9 + k] + w[o * 9 + k + 3]);
            wT[k * cout + o] = val * s;
        }
    } else {
        int tot = cout * cin;
        for (int e = i; e < tot; e += gridDim.x * blockDim.x) {
            int o = e / cin, k = e - o * cin;
            float s = g[o] * rsqrtf(rv[o] + 1e-5f);
            wT[k * cout + o] = w[e] * s;
        }
    }
}

// ------------------------- farthest point sampling -------------------------
template<int N, int NPOINT, int T>
__global__ void __launch_bounds__(T) fps_kernel(const float* __restrict__ xyz,
                                                float* __restrict__ newxyz)
{
    constexpr int PPT = N / T;
    int b = blockIdx.x;
    int tid = threadIdx.x;
    const float* x = xyz + (size_t)b * N * 3;

    float px[PPT], py[PPT], pz[PPT], dist[PPT];
#pragma unroll
    for (int i = 0; i < PPT; i++) {
        int p = tid + i * T;
        px[i] = x[p * 3 + 0];
        py[i] = x[p * 3 + 1];
        pz[i] = x[p * 3 + 2];
        dist[i] = 1e10f;
    }

    __shared__ float cur[3];
    __shared__ float wv[T / 32];
    __shared__ int   wi[T / 32];

    if (tid == 0) {
        cur[0] = x[0]; cur[1] = x[1]; cur[2] = x[2];
        float* o = newxyz + (size_t)b * NPOINT * 3;
        o[0] = x[0]; o[1] = x[1]; o[2] = x[2];
    }
    __syncthreads();

    for (int j = 1; j < NPOINT; j++) {
        float cx = cur[0], cy = cur[1], cz = cur[2];
        float bv = -1.0f;
        int   bi = 0x7fffffff;
#pragma unroll
        for (int i = 0; i < PPT; i++) {
            float dx = px[i] - cx, dy = py[i] - cy, dz = pz[i] - cz;
            float d = __fadd_rn(__fadd_rn(__fmul_rn(dx, dx), __fmul_rn(dy, dy)),
                                __fmul_rn(dz, dz));
            float nd = fminf(dist[i], d);
            dist[i] = nd;
            int gidx = tid + i * T;
            if (nd > bv || (nd == bv && gidx < bi)) { bv = nd; bi = gidx; }
        }
#pragma unroll
        for (int off = 16; off > 0; off >>= 1) {
            float ov = __shfl_down_sync(0xffffffffu, bv, off);
            int   oi = __shfl_down_sync(0xffffffffu, bi, off);
            if (ov > bv || (ov == bv && oi < bi)) { bv = ov; bi = oi; }
        }
        if ((tid & 31) == 0) { wv[tid >> 5] = bv; wi[tid >> 5] = bi; }
        __syncthreads();
        if (tid < 32) {
            constexpr int NW = T / 32;
            bv = (tid < NW) ? wv[tid] : -2.0f;
            bi = (tid < NW) ? wi[tid] : 0x7fffffff;
#pragma unroll
            for (int off = 16; off > 0; off >>= 1) {
                float ov = __shfl_down_sync(0xffffffffu, bv, off);
                int   oi = __shfl_down_sync(0xffffffffu, bi, off);
                if (ov > bv || (ov == bv && oi < bi)) { bv = ov; bi = oi; }
            }
            if (tid == 0) {
                const float* p = x + (size_t)bi * 3;
                float nx = p[0], ny = p[1], nz = p[2];
                cur[0] = nx; cur[1] = ny; cur[2] = nz;
                float* o = newxyz + ((size_t)b * NPOINT + j) * 3;
                o[0] = nx; o[1] = ny; o[2] = nz;
            }
        }
        __syncthreads();
    }
}

// ------------------------- ball query --------------------------------------
template<int NS>
__global__ void ballquery_kernel(const float* __restrict__ newxyz,
                                 const float* __restrict__ xyz,
                                 int* __restrict__ idxout,
                                 int N, int S, float rr)
{
    __shared__ int rows[4][NS];
    int lane = threadIdx.x & 31;
    int wip  = threadIdx.x >> 5;
    int q = blockIdx.x * 4 + wip;
    int b = q / S;
    const float* nq = newxyz + (size_t)q * 3;
    float qx = nq[0], qy = nq[1], qz = nq[2];
    const float* x = xyz + (size_t)b * N * 3;
    int* row = rows[wip];
    int cnt = 0;

    for (int base = 0; base < N; base += 32) {
        if (cnt >= NS) break;
        int p = base + lane;
        float dx = x[p * 3 + 0] - qx;
        float dy = x[p * 3 + 1] - qy;
        float dz = x[p * 3 + 2] - qz;
        float d = __fadd_rn(__fadd_rn(__fmul_rn(dx, dx), __fmul_rn(dy, dy)),
                            __fmul_rn(dz, dz));
        bool hit = d < rr;
        unsigned m = __ballot_sync(0xffffffffu, hit);
        if (hit) {
            int pos = cnt + __popc(m & ((1u << lane) - 1u));
            if (pos < NS) row[pos] = p;
        }
        cnt += __popc(m);
    }
    __syncwarp();
    int first = (cnt > 0) ? row[0] : 0;
    for (int t = cnt + lane; t < NS; t += 32) row[t] = first;
    __syncwarp();
    for (int t = lane; t < NS; t += 32) idxout[(size_t)q * NS + t] = row[t];
}

// ------------------------- fused group + MLP(2) + maxpool ------------------
// G groups per block, SB = G*NS samples. Thread tile = 4 channels x NO
// samples. Per k: 1 LDG.128 (weights) + NO/4 LDS.128 (broadcast) + 2*NO FFMA2.
template<int CIN, int C0, int C1, int NS, int G, int T, int NO0, int NO1,
         bool STAGE0, bool FINAL>
__global__ void __launch_bounds__(T) sa_mlp_kernel(
    const float* __restrict__ xyz, const float* __restrict__ feats,
    const float* __restrict__ newxyz, const int* __restrict__ idx,
    const float* __restrict__ w0T, const float* __restrict__ b0,
    const float* __restrict__ w1T, const float* __restrict__ b1,
    float* __restrict__ out, int N, int S)
{
    constexpr int SB = NS * G;
    constexpr int LD = SB + 4;
    constexpr int CQ0 = C0 / 4, NGRP0 = SB / NO0;
    constexpr int CQ1 = C1 / 4, NGRP1 = SB / NO1;
    static_assert(CQ0 * NGRP0 == T, "layer0 mapping");
    static_assert(CQ1 * NGRP1 == T, "layer1 mapping");
    static_assert(NS % NO1 == 0, "NO1 group alignment");
    constexpr int OPG = NS / NO1;            // pmax entries per group

    extern __shared__ __align__(16) float smem[];
    float* xs   = smem;                       // CIN * LD
    float* mid  = xs + CIN * LD;              // C0 * LD
    float* pmax = mid + C0 * LD;              // max(NGRP1*C1, SB ints) floats

    int gs0 = blockIdx.x * G;
    int b = gs0 / S;
    int tid = threadIdx.x;

    // ---- gather sample indices into smem (pmax region is free now) ----
    int* sidx = (int*)pmax;
    for (int e = tid; e < SB; e += T)
        sidx[e] = idx[(size_t)(gs0 + e / NS) * NS + (e % NS)];
    __syncthreads();

    // ---- gather xyz rows ----
    for (int e = tid; e < SB; e += T) {
        int g = e / NS;
        int id = sidx[e];
        const float* p = xyz + ((size_t)b * N + id) * 3;
        const float* c = newxyz + (size_t)(gs0 + g) * 3;
        float ax = p[0], ay = p[1], az = p[2];
        xs[0 * LD + e] = ax - c[0];
        xs[1 * LD + e] = ay - c[1];
        xs[2 * LD + e] = az - c[2];
        if (STAGE0) {
            xs[3 * LD + e] = ax; xs[4 * LD + e] = ay; xs[5 * LD + e] = az;
        }
    }
    if constexpr (!STAGE0) {
        constexpr int CF = CIN - 3;
        for (int e = tid; e < CF * SB; e += T) {
            int n = e / CF, c = e - n * CF;
            xs[(3 + c) * LD + n] = feats[((size_t)b * N + sidx[n]) * CF + c];
        }
    }
    __syncthreads();

    // ---- layer 0: xs[CIN x SB] -> mid[C0 x SB], relu ----
    {
        int cq = tid % CQ0;
        int n8 = tid / CQ0;
        u64 acc[4][NO0 / 2];
        {
            float4 bv = *reinterpret_cast<const float4*>(b0 + 4 * cq);
            float bk[4] = {bv.x, bv.y, bv.z, bv.w};
#pragma unroll
            for (int i = 0; i < 4; i++) {
                u64 p = pack2(bk[i]);
#pragma unroll
                for (int j = 0; j < NO0 / 2; j++) acc[i][j] = p;
            }
        }
        const float* xrow = xs + n8 * NO0;
        const float* wptr = w0T + 4 * cq;
#pragma unroll 2
        for (int k = 0; k < CIN; k++) {
            float4 w = *reinterpret_cast<const float4*>(wptr + k * C0);
            ulonglong2 v[NO0 / 4];
            const ulonglong2* xr = reinterpret_cast<const ulonglong2*>(xrow + k * LD);
#pragma unroll
            for (int j = 0; j < NO0 / 4; j++) v[j] = xr[j];
            float wk[4] = {w.x, w.y, w.z, w.w};
#pragma unroll
            for (int i = 0; i < 4; i++) {
                u64 w2 = pack2(wk[i]);
#pragma unroll
                for (int j = 0; j < NO0 / 4; j++) {
                    acc[i][2 * j + 0] = ffma2(w2, v[j].x, acc[i][2 * j + 0]);
                    acc[i][2 * j + 1] = ffma2(w2, v[j].y, acc[i][2 * j + 1]);
                }
            }
        }
#pragma unroll
        for (int i = 0; i < 4; i++) {
            float* mrow = mid + (4 * cq + i) * LD + n8 * NO0;
#pragma unroll
            for (int j = 0; j < NO0 / 2; j++) {
                float lo, hi;
                unpack2(acc[i][j], lo, hi);
                float2 r;
                r.x = fmaxf(lo, 0.0f);
                r.y = fmaxf(hi, 0.0f);
                *reinterpret_cast<float2*>(mrow + 2 * j) = r;
            }
        }
    }
    __syncthreads();

    // ---- layer 1: mid[C0 x SB] -> per-thread max over its NO1 samples ----
    {
        int cq = tid % CQ1;
        int n8 = tid / CQ1;
        u64 acc[4][NO1 / 2];
        {
            float4 bv = *reinterpret_cast<const float4*>(b1 + 4 * cq);
            float bk[4] = {bv.x, bv.y, bv.z, bv.w};
#pragma unroll
            for (int i = 0; i < 4; i++) {
                u64 p = pack2(bk[i]);
#pragma unroll
                for (int j = 0; j < NO1 / 2; j++) acc[i][j] = p;
            }
        }
        const float* mrowb = mid + n8 * NO1;
        const float* wptr = w1T + 4 * cq;
#pragma unroll 2
        for (int k = 0; k < C0; k++) {
            float4 w = *reinterpret_cast<const float4*>(wptr + k * C1);
            ulonglong2 v[NO1 / 4];
            const ulonglong2* mr = reinterpret_cast<const ulonglong2*>(mrowb + k * LD);
#pragma unroll
            for (int j = 0; j < NO1 / 4; j++) v[j] = mr[j];
            float wk[4] = {w.x, w.y, w.z, w.w};
#pragma unroll
            for (int i = 0; i < 4; i++) {
                u64 w2 = pack2(wk[i]);
#pragma unroll
                for (int j = 0; j < NO1 / 4; j++) {
                    acc[i][2 * j + 0] = ffma2(w2, v[j].x, acc[i][2 * j + 0]);
                    acc[i][2 * j + 1] = ffma2(w2, v[j].y, acc[i][2 * j + 1]);
                }
            }
        }
#pragma unroll
        for (int i = 0; i < 4; i++) {
            float m = -3.4e38f;
#pragma unroll
            for (int j = 0; j < NO1 / 2; j++) {
                float lo, hi;
                unpack2(acc[i][j], lo, hi);
                m = fmaxf(m, fmaxf(lo, hi));
            }
            pmax[n8 * C1 + 4 * cq + i] = m;
        }
    }
    __syncthreads();

    // ---- final per-group max + relu + store ----
    for (int e = tid; e < G * C1; e += T) {
        int g = e / C1, ch = e - g * C1;
        float m = pmax[(g * OPG) * C1 + ch];
#pragma unroll
        for (int j = 1; j < OPG; j++)
            m = fmaxf(m, pmax[(g * OPG + j) * C1 + ch]);
        m = fmaxf(m, 0.0f);
        int gs = gs0 + g;
        int s = gs - b * S;
        if (FINAL)
            out[(size_t)b * C1 * S + (size_t)ch * S + s] = m;   // (B, C, S)
        else
            out[(size_t)gs * C1 + ch] = m;                      // (B, S, C)
    }
}

// ---------------------------------------------------------------------------
extern "C" void kernel_launch(void* const* d_in, const int* in_sizes, int n_in,
                              void* d_out, int out_size)
{
    (void)in_sizes; (void)n_in; (void)out_size;
    const float* pc = (const float*)d_in[0];

    float *nx1, *nx2, *nx3, *f1, *f2;
    int* idxb;
    float *w0T, *w1T, *w2T, *w3T, *w4T, *w5T;
    float *b0, *b1, *b2, *b3, *b4, *b5;
    cudaGetSymbolAddress((void**)&nx1, g_nx1);
    cudaGetSymbolAddress((void**)&nx2, g_nx2);
    cudaGetSymbolAddress((void**)&nx3, g_nx3);
    cudaGetSymbolAddress((void**)&idxb, g_idxbuf);
    cudaGetSymbolAddress((void**)&f1, g_f1);
    cudaGetSymbolAddress((void**)&f2, g_f2);
    cudaGetSymbolAddress((void**)&w0T, g_w0T); cudaGetSymbolAddress((void**)&b0, g_b0);
    cudaGetSymbolAddress((void**)&w1T, g_w1T); cudaGetSymbolAddress((void**)&b1, g_b1);
    cudaGetSymbolAddress((void**)&w2T, g_w2T); cudaGetSymbolAddress((void**)&b2, g_b2);
    cudaGetSymbolAddress((void**)&w3T, g_w3T); cudaGetSymbolAddress((void**)&b3, g_b3);
    cudaGetSymbolAddress((void**)&w4T, g_w4T); cudaGetSymbolAddress((void**)&b4, g_b4);
    cudaGetSymbolAddress((void**)&w5T, g_w5T); cudaGetSymbolAddress((void**)&b5, g_b5);

    FoldArgs fa;
    const int cins[6]  = {9, 32, 67, 128, 131, 256};
    const int couts[6] = {32, 64, 128, 128, 256, 256};
    float* wTs[6] = {w0T, w1T, w2T, w3T, w4T, w5T};
    float* bss[6] = {b0, b1, b2, b3, b4, b5};
    for (int l = 0; l < 6; l++) {
        fa.w[l]  = (const float*)d_in[1 + 5 * l];
        fa.g[l]  = (const float*)d_in[2 + 5 * l];
        fa.be[l] = (const float*)d_in[3 + 5 * l];
        fa.rm[l] = (const float*)d_in[4 + 5 * l];
        fa.rv[l] = (const float*)d_in[5 + 5 * l];
        fa.wT[l] = wTs[l]; fa.bias[l] = bss[l];
        fa.cin[l] = cins[l]; fa.cout[l] = couts[l];
    }
    fold_all_kernel<<<dim3(72, 6), 256>>>(fa);

    const float rr0 = (float)(0.02 * 0.02);
    const float rr1 = (float)(0.04 * 0.04);
    const float rr2 = (float)(0.08 * 0.08);

    // dynamic smem sizes (floats): (CIN+C0)*LD + 512 (pmax)
    const int smem0 = ((6   + 32 ) * 132 + 512) * 4;   // 22112 B
    const int smem1 = ((67  + 128) * 68  + 512) * 4;   // 55088 B
    const int smem2 = ((131 + 256) * 36  + 512) * 4;   // 57776 B

    // stage0: 9(->6)->32->64, NS=32, G=4, T=128, NO0=8, NO1=16
    auto k0 = sa_mlp_kernel<6, 32, 64, 32, 4, 128, 8, 16, true, false>;
    // stage1: 67->128->128, NS=32, G=2, T=128, NO0=16, NO1=16
    auto k1 = sa_mlp_kernel<67, 128, 128, 32, 2, 128, 16, 16, false, false>;
    // stage2: 131->256->256, NS=16, G=2, T=128, NO0=16, NO1=16
    auto k2 = sa_mlp_kernel<131, 256, 256, 16, 2, 128, 16, 16, false, true>;

    cudaFuncSetAttribute((const void*)k1, cudaFuncAttributeMaxDynamicSharedMemorySize, smem1);
    cudaFuncSetAttribute((const void*)k2, cudaFuncAttributeMaxDynamicSharedMemorySize, smem2);

    // ---- stage 0: N=4096 -> S=128 ----
    fps_kernel<4096, 128, 256><<<B, 256>>>(pc, nx1);
    ballquery_kernel<32><<<(B * S0) / 4, 128>>>(nx1, pc, idxb, N0, S0, rr0);
    k0<<<(B * S0) / 4, 128, smem0>>>(pc, nullptr, nx1, idxb, w0T, b0, w1T, b1, f1, N0, S0);

    // ---- stage 1: N=128 -> S=64 ----
    fps_kernel<128, 64, 128><<<B, 128>>>(nx1, nx2);
    ballquery_kernel<32><<<(B * S1) / 4, 128>>>(nx2, nx1, idxb, S0, S1, rr1);
    k1<<<(B * S1) / 2, 128, smem1>>>(nx1, f1, nx2, idxb, w2T, b2, w3T, b3, f2, S0, S1);

    // ---- stage 2: N=64 -> S=32 ----
    fps_kernel<64, 32, 64><<<B, 64>>>(nx2, nx3);
    ballquery_kernel<16><<<(B * S2) / 4, 128>>>(nx3, nx2, idxb, S1, S2, rr2);
    k2<<<(B * S2) / 2, 128, smem2>>>(nx2, f2, nx3, idxb, w4T, b4, w5T, b5, (float*)d_out, S1, S2);
}

// round 7
// speedup vs baseline: 1.1243x; 1.1243x over previous
#include <cuda_runtime.h>
#include <cstdint>

// ---------------------------------------------------------------------------
// PointNet++ (3 SA stages), B=64, N=4096, fp32.
// Round 6: stage1/2 back to R4 high-occupancy config (G=1, NO=8, ~30KB smem,
// 8 blocks/SM); stage0 keeps R5 improvements (folded CIN=6, G=4); fps0 T=512.
// ---------------------------------------------------------------------------

static constexpr int B   = 64;
static constexpr int N0  = 4096;
static constexpr int S0  = 128, NSAMP0 = 32;
static constexpr int S1  = 64;
static constexpr int S2  = 32;

// ------------------------- device scratch (no allocs) ----------------------
__device__ float g_nx1[B * S0 * 3];
__device__ float g_nx2[B * S1 * 3];
__device__ float g_nx3[B * S2 * 3];
__device__ int   g_idxbuf[B * S0 * NSAMP0];
__device__ float g_f1[B * S0 * 64];
__device__ float g_f2[B * S1 * 128];

// k-major folded weights: wT[k*Cout + o]. Layer0 folded to 6 rows
// (rows 3..5 = W[:,3:6]+W[:,6:9], since stage-0 feats duplicate abs xyz).
__device__ __align__(16) float g_w0T[6 * 32];     __device__ __align__(16) float g_b0[32];
__device__ __align__(16) float g_w1T[32 * 64];    __device__ __align__(16) float g_b1[64];
__device__ __align__(16) float g_w2T[67 * 128];   __device__ __align__(16) float g_b2[128];
__device__ __align__(16) float g_w3T[128 * 128];  __device__ __align__(16) float g_b3[128];
__device__ __align__(16) float g_w4T[131 * 256];  __device__ __align__(16) float g_b4[256];
__device__ __align__(16) float g_w5T[256 * 256];  __device__ __align__(16) float g_b5[256];

// ------------------------- f32x2 helpers -----------------------------------
typedef unsigned long long u64;

__device__ __forceinline__ u64 pack2(float x) {
    u64 r;
    asm("mov.b64 %0, {%1, %2};" : "=l"(r) : "f"(x), "f"(x));
    return r;
}
__device__ __forceinline__ void unpack2(u64 v, float& lo, float& hi) {
    asm("mov.b64 {%0, %1}, %2;" : "=f"(lo), "=f"(hi) : "l"(v));
}
__device__ __forceinline__ u64 ffma2(u64 a, u64 b, u64 c) {
    u64 d;
    asm("fma.rn.f32x2 %0, %1, %2, %3;" : "=l"(d) : "l"(a), "l"(b), "l"(c));
    return d;
}

// ------------------------- merged BN fold (k-major) ------------------------
struct FoldArgs {
    const float* w[6]; const float* g[6]; const float* be[6];
    const float* rm[6]; const float* rv[6];
    float* wT[6]; float* bias[6];
    int cin[6]; int cout[6];
};

__global__ void fold_all_kernel(FoldArgs a)
{
    int l = blockIdx.y;
    int cin = a.cin[l], cout = a.cout[l];
    const float* w = a.w[l]; const float* g = a.g[l]; const float* be = a.be[l];
    const float* rm = a.rm[l]; const float* rv = a.rv[l];
    float* wT = a.wT[l]; float* bias = a.bias[l];
    int i = blockIdx.x * blockDim.x + threadIdx.x;
    if (i < cout) {
        float s = g[i] * rsqrtf(rv[i] + 1e-5f);
        bias[i] = be[i] - s * rm[i];
    }
    if (l == 0) {
        // fold 9 -> 6 rows: rows 0..2 as-is, rows 3..5 = W[:,3+t] + W[:,6+t]
        int tot = cout * 6;
        for (int e = i; e < tot; e += gridDim.x * blockDim.x) {
            int o = e / 6, k = e - o * 6;
            float s = g[o] * rsqrtf(rv[o] + 1e-5f);
            float val = (k < 3) ? w[o * 9 + k] : (w[o * 9 + k] + w[o * 9 + k + 3]);
            wT[k * cout + o] = val * s;
        }
    } else {
        int tot = cout * cin;
        for (int e = i; e < tot; e += gridDim.x * blockDim.x) {
            int o = e / cin, k = e - o * cin;
            float s = g[o] * rsqrtf(rv[o] + 1e-5f);
            wT[k * cout + o] = w[e] * s;
        }
    }
}

// ------------------------- farthest point sampling -------------------------
template<int N, int NPOINT, int T>
__global__ void __launch_bounds__(T) fps_kernel(const float* __restrict__ xyz,
                                                float* __restrict__ newxyz)
{
    constexpr int PPT = N / T;
    int b = blockIdx.x;
    int tid = threadIdx.x;
    const float* x = xyz + (size_t)b * N * 3;

    float px[PPT], py[PPT], pz[PPT], dist[PPT];
#pragma unroll
    for (int i = 0; i < PPT; i++) {
        int p = tid + i * T;
        px[i] = x[p * 3 + 0];
        py[i] = x[p * 3 + 1];
        pz[i] = x[p * 3 + 2];
        dist[i] = 1e10f;
    }

    __shared__ float cur[3];
    __shared__ float wv[T / 32];
    __shared__ int   wi[T / 32];

    if (tid == 0) {
        cur[0] = x[0]; cur[1] = x[1]; cur[2] = x[2];
        float* o = newxyz + (size_t)b * NPOINT * 3;
        o[0] = x[0]; o[1] = x[1]; o[2] = x[2];
    }
    __syncthreads();

    for (int j = 1; j < NPOINT; j++) {
        float cx = cur[0], cy = cur[1], cz = cur[2];
        float bv = -1.0f;
        int   bi = 0x7fffffff;
#pragma unroll
        for (int i = 0; i < PPT; i++) {
            float dx = px[i] - cx, dy = py[i] - cy, dz = pz[i] - cz;
            float d = __fadd_rn(__fadd_rn(__fmul_rn(dx, dx), __fmul_rn(dy, dy)),
                                __fmul_rn(dz, dz));
            float nd = fminf(dist[i], d);
            dist[i] = nd;
            int gidx = tid + i * T;
            if (nd > bv || (nd == bv && gidx < bi)) { bv = nd; bi = gidx; }
        }
#pragma unroll
        for (int off = 16; off > 0; off >>= 1) {
            float ov = __shfl_down_sync(0xffffffffu, bv, off);
            int   oi = __shfl_down_sync(0xffffffffu, bi, off);
            if (ov > bv || (ov == bv && oi < bi)) { bv = ov; bi = oi; }
        }
        if ((tid & 31) == 0) { wv[tid >> 5] = bv; wi[tid >> 5] = bi; }
        __syncthreads();
        if (tid < 32) {
            constexpr int NW = T / 32;
            bv = (tid < NW) ? wv[tid] : -2.0f;
            bi = (tid < NW) ? wi[tid] : 0x7fffffff;
#pragma unroll
            for (int off = 16; off > 0; off >>= 1) {
                float ov = __shfl_down_sync(0xffffffffu, bv, off);
                int   oi = __shfl_down_sync(0xffffffffu, bi, off);
                if (ov > bv || (ov == bv && oi < bi)) { bv = ov; bi = oi; }
            }
            if (tid == 0) {
                const float* p = x + (size_t)bi * 3;
                float nx = p[0], ny = p[1], nz = p[2];
                cur[0] = nx; cur[1] = ny; cur[2] = nz;
                float* o = newxyz + ((size_t)b * NPOINT + j) * 3;
                o[0] = nx; o[1] = ny; o[2] = nz;
            }
        }
        __syncthreads();
    }
}

// ------------------------- ball query --------------------------------------
template<int NS>
__global__ void ballquery_kernel(const float* __restrict__ newxyz,
                                 const float* __restrict__ xyz,
                                 int* __restrict__ idxout,
                                 int N, int S, float rr)
{
    __shared__ int rows[4][NS];
    int lane = threadIdx.x & 31;
    int wip  = threadIdx.x >> 5;
    int q = blockIdx.x * 4 + wip;
    int b = q / S;
    const float* nq = newxyz + (size_t)q * 3;
    float qx = nq[0], qy = nq[1], qz = nq[2];
    const float* x = xyz + (size_t)b * N * 3;
    int* row = rows[wip];
    int cnt = 0;

    for (int base = 0; base < N; base += 32) {
        if (cnt >= NS) break;
        int p = base + lane;
        float dx = x[p * 3 + 0] - qx;
        float dy = x[p * 3 + 1] - qy;
        float dz = x[p * 3 + 2] - qz;
        float d = __fadd_rn(__fadd_rn(__fmul_rn(dx, dx), __fmul_rn(dy, dy)),
                            __fmul_rn(dz, dz));
        bool hit = d < rr;
        unsigned m = __ballot_sync(0xffffffffu, hit);
        if (hit) {
            int pos = cnt + __popc(m & ((1u << lane) - 1u));
            if (pos < NS) row[pos] = p;
        }
        cnt += __popc(m);
    }
    __syncwarp();
    int first = (cnt > 0) ? row[0] : 0;
    for (int t = cnt + lane; t < NS; t += 32) row[t] = first;
    __syncwarp();
    for (int t = lane; t < NS; t += 32) idxout[(size_t)q * NS + t] = row[t];
}

// ------------------------- fused group + MLP(2) + maxpool ------------------
// G groups per block, SB = G*NS samples. Thread tile = 4 channels x NO
// samples. Per k: 1 LDG.128 (weights) + NO/4 LDS.128 (broadcast) + 2*NO FFMA2.
template<int CIN, int C0, int C1, int NS, int G, int T, int NO0, int NO1,
         bool STAGE0, bool FINAL>
__global__ void __launch_bounds__(T) sa_mlp_kernel(
    const float* __restrict__ xyz, const float* __restrict__ feats,
    const float* __restrict__ newxyz, const int* __restrict__ idx,
    const float* __restrict__ w0T, const float* __restrict__ b0,
    const float* __restrict__ w1T, const float* __restrict__ b1,
    float* __restrict__ out, int N, int S)
{
    constexpr int SB = NS * G;
    constexpr int LD = SB + 4;
    constexpr int CQ0 = C0 / 4, NGRP0 = SB / NO0;
    constexpr int CQ1 = C1 / 4, NGRP1 = SB / NO1;
    static_assert(CQ0 * NGRP0 == T, "layer0 mapping");
    static_assert(CQ1 * NGRP1 == T, "layer1 mapping");
    static_assert(NS % NO1 == 0, "NO1 group alignment");
    constexpr int OPG = NS / NO1;            // pmax entries per group
    constexpr int PMAXF = (NGRP1 * C1 > SB) ? NGRP1 * C1 : SB;

    extern __shared__ __align__(16) float smem[];
    float* xs   = smem;                       // CIN * LD
    float* mid  = xs + CIN * LD;              // C0 * LD
    float* pmax = mid + C0 * LD;              // PMAXF floats

    int gs0 = blockIdx.x * G;
    int b = gs0 / S;
    int tid = threadIdx.x;

    // ---- gather sample indices into smem (pmax region is free now) ----
    int* sidx = (int*)pmax;
    for (int e = tid; e < SB; e += T)
        sidx[e] = idx[(size_t)(gs0 + e / NS) * NS + (e % NS)];
    __syncthreads();

    // ---- gather xyz rows ----
    for (int e = tid; e < SB; e += T) {
        int g = e / NS;
        int id = sidx[e];
        const float* p = xyz + ((size_t)b * N + id) * 3;
        const float* c = newxyz + (size_t)(gs0 + g) * 3;
        float ax = p[0], ay = p[1], az = p[2];
        xs[0 * LD + e] = ax - c[0];
        xs[1 * LD + e] = ay - c[1];
        xs[2 * LD + e] = az - c[2];
        if (STAGE0) {
            xs[3 * LD + e] = ax; xs[4 * LD + e] = ay; xs[5 * LD + e] = az;
        }
    }
    if constexpr (!STAGE0) {
        constexpr int CF = CIN - 3;
        for (int e = tid; e < CF * SB; e += T) {
            int n = e / CF, c = e - n * CF;
            xs[(3 + c) * LD + n] = feats[((size_t)b * N + sidx[n]) * CF + c];
        }
    }
    __syncthreads();

    // ---- layer 0: xs[CIN x SB] -> mid[C0 x SB], relu ----
    {
        int cq = tid % CQ0;
        int n8 = tid / CQ0;
        u64 acc[4][NO0 / 2];
        {
            float4 bv = *reinterpret_cast<const float4*>(b0 + 4 * cq);
            float bk[4] = {bv.x, bv.y, bv.z, bv.w};
#pragma unroll
            for (int i = 0; i < 4; i++) {
                u64 p = pack2(bk[i]);
#pragma unroll
                for (int j = 0; j < NO0 / 2; j++) acc[i][j] = p;
            }
        }
        const float* xrow = xs + n8 * NO0;
        const float* wptr = w0T + 4 * cq;
#pragma unroll 4
        for (int k = 0; k < CIN; k++) {
            float4 w = *reinterpret_cast<const float4*>(wptr + k * C0);
            ulonglong2 v[NO0 / 4];
            const ulonglong2* xr = reinterpret_cast<const ulonglong2*>(xrow + k * LD);
#pragma unroll
            for (int j = 0; j < NO0 / 4; j++) v[j] = xr[j];
            float wk[4] = {w.x, w.y, w.z, w.w};
#pragma unroll
            for (int i = 0; i < 4; i++) {
                u64 w2 = pack2(wk[i]);
#pragma unroll
                for (int j = 0; j < NO0 / 4; j++) {
                    acc[i][2 * j + 0] = ffma2(w2, v[j].x, acc[i][2 * j + 0]);
                    acc[i][2 * j + 1] = ffma2(w2, v[j].y, acc[i][2 * j + 1]);
                }
            }
        }
#pragma unroll
        for (int i = 0; i < 4; i++) {
            float* mrow = mid + (4 * cq + i) * LD + n8 * NO0;
#pragma unroll
            for (int j = 0; j < NO0 / 2; j++) {
                float lo, hi;
                unpack2(acc[i][j], lo, hi);
                float2 r;
                r.x = fmaxf(lo, 0.0f);
                r.y = fmaxf(hi, 0.0f);
                *reinterpret_cast<float2*>(mrow + 2 * j) = r;
            }
        }
    }
    __syncthreads();

    // ---- layer 1: mid[C0 x SB] -> per-thread max over its NO1 samples ----
    {
        int cq = tid % CQ1;
        int n8 = tid / CQ1;
        u64 acc[4][NO1 / 2];
        {
            float4 bv = *reinterpret_cast<const float4*>(b1 + 4 * cq);
            float bk[4] = {bv.x, bv.y, bv.z, bv.w};
#pragma unroll
            for (int i = 0; i < 4; i++) {
                u64 p = pack2(bk[i]);
#pragma unroll
                for (int j = 0; j < NO1 / 2; j++) acc[i][j] = p;
            }
        }
        const float* mrowb = mid + n8 * NO1;
        const float* wptr = w1T + 4 * cq;
#pragma unroll 4
        for (int k = 0; k < C0; k++) {
            float4 w = *reinterpret_cast<const float4*>(wptr + k * C1);
            ulonglong2 v[NO1 / 4];
            const ulonglong2* mr = reinterpret_cast<const ulonglong2*>(mrowb + k * LD);
#pragma unroll
            for (int j = 0; j < NO1 / 4; j++) v[j] = mr[j];
            float wk[4] = {w.x, w.y, w.z, w.w};
#pragma unroll
            for (int i = 0; i < 4; i++) {
                u64 w2 = pack2(wk[i]);
#pragma unroll
                for (int j = 0; j < NO1 / 4; j++) {
                    acc[i][2 * j + 0] = ffma2(w2, v[j].x, acc[i][2 * j + 0]);
                    acc[i][2 * j + 1] = ffma2(w2, v[j].y, acc[i][2 * j + 1]);
                }
            }
        }
#pragma unroll
        for (int i = 0; i < 4; i++) {
            float m = -3.4e38f;
#pragma unroll
            for (int j = 0; j < NO1 / 2; j++) {
                float lo, hi;
                unpack2(acc[i][j], lo, hi);
                m = fmaxf(m, fmaxf(lo, hi));
            }
            pmax[n8 * C1 + 4 * cq + i] = m;
        }
    }
    __syncthreads();

    // ---- final per-group max + relu + store ----
    for (int e = tid; e < G * C1; e += T) {
        int g = e / C1, ch = e - g * C1;
        float m = pmax[(g * OPG) * C1 + ch];
#pragma unroll
        for (int j = 1; j < OPG; j++)
            m = fmaxf(m, pmax[(g * OPG + j) * C1 + ch]);
        m = fmaxf(m, 0.0f);
        int gs = gs0 + g;
        int s = gs - b * S;
        if (FINAL)
            out[(size_t)b * C1 * S + (size_t)ch * S + s] = m;   // (B, C, S)
        else
            out[(size_t)gs * C1 + ch] = m;                      // (B, S, C)
    }
}

// ---------------------------------------------------------------------------
extern "C" void kernel_launch(void* const* d_in, const int* in_sizes, int n_in,
                              void* d_out, int out_size)
{
    (void)in_sizes; (void)n_in; (void)out_size;
    const float* pc = (const float*)d_in[0];

    float *nx1, *nx2, *nx3, *f1, *f2;
    int* idxb;
    float *w0T, *w1T, *w2T, *w3T, *w4T, *w5T;
    float *b0, *b1, *b2, *b3, *b4, *b5;
    cudaGetSymbolAddress((void**)&nx1, g_nx1);
    cudaGetSymbolAddress((void**)&nx2, g_nx2);
    cudaGetSymbolAddress((void**)&nx3, g_nx3);
    cudaGetSymbolAddress((void**)&idxb, g_idxbuf);
    cudaGetSymbolAddress((void**)&f1, g_f1);
    cudaGetSymbolAddress((void**)&f2, g_f2);
    cudaGetSymbolAddress((void**)&w0T, g_w0T); cudaGetSymbolAddress((void**)&b0, g_b0);
    cudaGetSymbolAddress((void**)&w1T, g_w1T); cudaGetSymbolAddress((void**)&b1, g_b1);
    cudaGetSymbolAddress((void**)&w2T, g_w2T); cudaGetSymbolAddress((void**)&b2, g_b2);
    cudaGetSymbolAddress((void**)&w3T, g_w3T); cudaGetSymbolAddress((void**)&b3, g_b3);
    cudaGetSymbolAddress((void**)&w4T, g_w4T); cudaGetSymbolAddress((void**)&b4, g_b4);
    cudaGetSymbolAddress((void**)&w5T, g_w5T); cudaGetSymbolAddress((void**)&b5, g_b5);

    FoldArgs fa;
    const int cins[6]  = {9, 32, 67, 128, 131, 256};
    const int couts[6] = {32, 64, 128, 128, 256, 256};
    float* wTs[6] = {w0T, w1T, w2T, w3T, w4T, w5T};
    float* bss[6] = {b0, b1, b2, b3, b4, b5};
    for (int l = 0; l < 6; l++) {
        fa.w[l]  = (const float*)d_in[1 + 5 * l];
        fa.g[l]  = (const float*)d_in[2 + 5 * l];
        fa.be[l] = (const float*)d_in[3 + 5 * l];
        fa.rm[l] = (const float*)d_in[4 + 5 * l];
        fa.rv[l] = (const float*)d_in[5 + 5 * l];
        fa.wT[l] = wTs[l]; fa.bias[l] = bss[l];
        fa.cin[l] = cins[l]; fa.cout[l] = couts[l];
    }
    fold_all_kernel<<<dim3(72, 6), 256>>>(fa);

    const float rr0 = (float)(0.02 * 0.02);
    const float rr1 = (float)(0.04 * 0.04);
    const float rr2 = (float)(0.08 * 0.08);

    // dynamic smem (bytes)
    const int smem0 = ((6   + 32 ) * 132 + 512) * 4;   // 22112
    const int smem1 = ((67  + 128) * 36  + 512) * 4;   // 30128
    const int smem2 = ((131 + 256) * 20  + 512) * 4;   // 33008

    // stage0: CIN(folded)=6 ->32->64, NS=32, G=4, T=128, NO0=8, NO1=16
    auto k0 = sa_mlp_kernel<6, 32, 64, 32, 4, 128, 8, 16, true, false>;
    // stage1: 67->128->128, NS=32, G=1, T=128, NO0=8, NO1=8  (R4 config)
    auto k1 = sa_mlp_kernel<67, 128, 128, 32, 1, 128, 8, 8, false, false>;
    // stage2: 131->256->256, NS=16, G=1, T=128, NO0=8, NO1=8 (R4 config)
    auto k2 = sa_mlp_kernel<131, 256, 256, 16, 1, 128, 8, 8, false, true>;

    // ---- stage 0: N=4096 -> S=128 ----
    fps_kernel<4096, 128, 512><<<B, 512>>>(pc, nx1);
    ballquery_kernel<32><<<(B * S0) / 4, 128>>>(nx1, pc, idxb, N0, S0, rr0);
    k0<<<(B * S0) / 4, 128, smem0>>>(pc, nullptr, nx1, idxb, w0T, b0, w1T, b1, f1, N0, S0);

    // ---- stage 1: N=128 -> S=64 ----
    fps_kernel<128, 64, 128><<<B, 128>>>(nx1, nx2);
    ballquery_kernel<32><<<(B * S1) / 4, 128>>>(nx2, nx1, idxb, S0, S1, rr1);
    k1<<<B * S1, 128, smem1>>>(nx1, f1, nx2, idxb, w2T, b2, w3T, b3, f2, S0, S1);

    // ---- stage 2: N=64 -> S=32 ----
    fps_kernel<64, 32, 64><<<B, 64>>>(nx2, nx3);
    ballquery_kernel<16><<<(B * S2) / 4, 128>>>(nx3, nx2, idxb, S1, S2, rr2);
    k2<<<B * S2, 128, smem2>>>(nx2, f2, nx3, idxb, w4T, b4, w5T, b5, (float*)d_out, S1, S2);
}